// round 6
// baseline (speedup 1.0000x reference)
#include <cuda_runtime.h>

#define K 7
#define HH 1024
#define WW 1024
#define NBINS (K * K)
#define TPB 256

// per-bin final scores (pre-divided by count and K^2); overwritten every run
__device__ float g_score[64];

__device__ __forceinline__ void bin_extents(float ci, float cj, float h, float w,
                                            int bi, int bj,
                                            int& r0, int& r1, int& c0, int& c1) {
    // Mirror the reference float32 arithmetic.
    float i0 = ci - h * 0.5f, i1 = ci + h * 0.5f;
    float j0 = cj - w * 0.5f, j1 = cj + w * 0.5f;
    float stepi = (i1 - i0) / (float)(K + 1);
    float stepj = (j1 - j0) / (float)(K + 1);
    float ic = i0 + (float)(bi + 1) * stepi;
    float jc = j0 + (float)(bj + 1) * stepj;
    float bh2 = h / (float)K * 0.5f;
    float bw2 = w / (float)K * 0.5f;
    r0 = (int)floorf((ic - bh2) * (float)HH);
    r1 = (int)ceilf ((ic + bh2) * (float)HH);
    c0 = (int)floorf((jc - bw2) * (float)WW);
    c1 = (int)ceilf ((jc + bw2) * (float)WW);
    r0 = max(r0, 0); r1 = min(r1, HH);
    c0 = max(c0, 0); c1 = min(c1, WW);
}

// Kernel 1: one block per bin. No atomics, no fences, no cross-block deps.
__global__ __launch_bounds__(TPB)
void psroi_bins_kernel(const float* __restrict__ x,
                       const float* __restrict__ region) {
    // let the dependent (finalize) grid start launching immediately
    cudaTriggerProgrammaticLaunchCompletion();

    const int bin  = blockIdx.x;           // 0..48
    const int bi   = bin / K, bj = bin % K;
    const int t    = threadIdx.x;
    const int wid  = t >> 5;
    const int lane = t & 31;

    const float4 reg = *reinterpret_cast<const float4*>(region);

    int r0, r1, c0, c1;
    bin_extents(reg.x, reg.y, reg.z, reg.w, bi, bj, r0, r1, c0, c1);

    const int total = (r1 - r0) * (c1 - c0);
    const float* __restrict__ chan = x + (size_t)bin * HH * WW;

    // warp-per-row, lane-per-column gather: no divisions, coalesced rows
    float acc = 0.0f;
    for (int r = r0 + wid; r < r1; r += TPB / 32) {
        const float* __restrict__ rowp = chan + (size_t)r * WW;
        for (int c = c0 + lane; c < c1; c += 32)
            acc += __ldg(rowp + c);
    }

    // warp shuffle reduce, then 8 warp-leaders -> warp 0 (deterministic)
    #pragma unroll
    for (int o = 16; o > 0; o >>= 1)
        acc += __shfl_down_sync(0xffffffffu, acc, o);

    __shared__ float s[TPB / 32];
    if (lane == 0) s[wid] = acc;
    __syncthreads();

    if (wid == 0) {
        float v = (lane < TPB / 32) ? s[lane] : 0.0f;
        #pragma unroll
        for (int o = 4; o > 0; o >>= 1)
            v += __shfl_down_sync(0xffffffffu, v, o);
        if (lane == 0)
            g_score[bin] = v / ((float)total * (float)NBINS);
    }
}

// Kernel 2: launched with PDL; parks until kernel 1's writes are visible,
// then sums 49 floats and stores the scalar.
__global__ __launch_bounds__(64)
void psroi_finalize_kernel(float* __restrict__ out) {
    cudaGridDependencySynchronize();

    const int t = threadIdx.x;
    float v = (t < NBINS) ? g_score[t] : 0.0f;

    __shared__ float s[2];
    #pragma unroll
    for (int o = 16; o > 0; o >>= 1)
        v += __shfl_down_sync(0xffffffffu, v, o);
    if ((t & 31) == 0) s[t >> 5] = v;
    __syncthreads();
    if (t == 0) out[0] = s[0] + s[1];
}

extern "C" void kernel_launch(void* const* d_in, const int* in_sizes, int n_in,
                              void* d_out, int out_size) {
    const float* x      = (const float*)d_in[0];
    const float* region = (const float*)d_in[1];
    float* out = (float*)d_out;

    psroi_bins_kernel<<<NBINS, TPB>>>(x, region);

    // finalize with programmatic dependent launch: launch overlaps kernel 1
    cudaLaunchConfig_t cfg = {};
    cfg.gridDim  = dim3(1);
    cfg.blockDim = dim3(64);
    cfg.stream   = 0;
    cudaLaunchAttribute attr[1];
    attr[0].id = cudaLaunchAttributeProgrammaticStreamSerialization;
    attr[0].val.programmaticStreamSerializationAllowed = 1;
    cfg.attrs    = attr;
    cfg.numAttrs = 1;
    cudaLaunchKernelEx(&cfg, psroi_finalize_kernel, out);
}